// round 6
// baseline (speedup 1.0000x reference)
#include <cuda_runtime.h>
#include <math.h>

#define Bq 8
#define Nq 1024
#define Cq 512
#define Hq 4
#define HDq 128
#define SCALEq 0.08838834764831845f

// ---------------- scratch ----------------
__device__ float g_q[Bq * Hq * Nq * HDq];
__device__ float g_k[Bq * Hq * Nq * HDq];
__device__ float g_v[Bq * Hq * Nq * HDq];
__device__ float g_s[(size_t)Bq * Hq * Nq * Nq]; // scores then probs (in place)
__device__ float g_y[Bq * Nq * Cq];

// ---------------- tf32 helpers ----------------
__device__ __forceinline__ unsigned f2tf(float f) {
    unsigned r;
    asm("cvt.rna.tf32.f32 %0, %1;" : "=r"(r) : "f"(f));
    return r;
}
__device__ __forceinline__ float tfr(float f) { return __uint_as_float(f2tf(f)); }
__device__ __forceinline__ void cvt4(float4& v) {
    v.x = tfr(v.x); v.y = tfr(v.y); v.z = tfr(v.z); v.w = tfr(v.w);
}

__device__ __forceinline__ void mma8(float c[4], const unsigned a[4], const unsigned b[2]) {
    asm volatile(
        "mma.sync.aligned.m16n8k8.row.col.f32.tf32.tf32.f32 "
        "{%0,%1,%2,%3},{%4,%5,%6,%7},{%8,%9},{%0,%1,%2,%3};"
        : "+f"(c[0]), "+f"(c[1]), "+f"(c[2]), "+f"(c[3])
        : "r"(a[0]), "r"(a[1]), "r"(a[2]), "r"(a[3]), "r"(b[0]), "r"(b[1]));
}

// fragment compute for one smem stage (both kk halves)
__device__ __forceinline__ void stage_compute(const float (*As)[20], const float (*Bs)[20],
                                              int wm, int wn, int lr, int lc,
                                              float c[4][4][4]) {
#pragma unroll
    for (int kk = 0; kk < 16; kk += 8) {
        unsigned a[4][4], b[4][2];
#pragma unroll
        for (int t = 0; t < 4; t++) {
            a[t][0] = __float_as_uint(As[wm + t * 16 + lr][kk + lc]);
            a[t][1] = __float_as_uint(As[wm + t * 16 + 8 + lr][kk + lc]);
            a[t][2] = __float_as_uint(As[wm + t * 16 + lr][kk + lc + 4]);
            a[t][3] = __float_as_uint(As[wm + t * 16 + 8 + lr][kk + lc + 4]);
        }
#pragma unroll
        for (int u = 0; u < 4; u++) {
            b[u][0] = __float_as_uint(Bs[wn + u * 8 + lr][kk + lc]);
            b[u][1] = __float_as_uint(Bs[wn + u * 8 + lr][kk + lc + 4]);
        }
#pragma unroll
        for (int t = 0; t < 4; t++)
#pragma unroll
            for (int u = 0; u < 4; u++) mma8(c[t][u], a[t], b[u]);
    }
}

// ======= core: C(128x128) = A(128xK) * B(128xK)^T, 256 thr, double-buffered ====
template <int K, bool CVTA, bool CVTB>
__device__ __forceinline__ void mma_abt2(const float* __restrict__ A, int lda,
                                         const float* __restrict__ B, int ldb,
                                         float c[4][4][4]) {
    __shared__ float As[2][128][20];
    __shared__ float Bs[2][128][20];
    const int tid = threadIdx.x, lane = tid & 31, wid = tid >> 5;
    const int wm = (wid & 1) * 64, wn = (wid >> 1) * 32;
    const int lr = lane >> 2, lc = lane & 3;
    const int gr = tid >> 2, gc = (tid & 3) * 4;   // 64 rows per pass, 2 passes

    float4 pa[2], pb[2];
    auto ld = [&](int k0) {
        pa[0] = *(const float4*)(A + (size_t)gr * lda + k0 + gc);
        pa[1] = *(const float4*)(A + (size_t)(gr + 64) * lda + k0 + gc);
        pb[0] = *(const float4*)(B + (size_t)gr * ldb + k0 + gc);
        pb[1] = *(const float4*)(B + (size_t)(gr + 64) * ldb + k0 + gc);
        if (CVTA) { cvt4(pa[0]); cvt4(pa[1]); }
        if (CVTB) { cvt4(pb[0]); cvt4(pb[1]); }
    };
    auto st = [&](int buf) {
#pragma unroll
        for (int i = 0; i < 2; i++) {
            *(float4*)&As[buf][gr + i * 64][gc] = pa[i];
            *(float4*)&Bs[buf][gr + i * 64][gc] = pb[i];
        }
    };

    ld(0); st(0);
    __syncthreads();
#pragma unroll 1
    for (int k0 = 0; k0 < K; k0 += 16) {
        const int cur = (k0 >> 4) & 1;
        const bool more = (k0 + 16) < K;
        if (more) ld(k0 + 16);
        stage_compute(As[cur], Bs[cur], wm, wn, lr, lc, c);
        if (more) {
            st(cur ^ 1);
            __syncthreads();
        }
    }
}

// ======= core: C(128x128) = A(128x1024) * B(1024x128), B row-major k x n =======
__device__ __forceinline__ void mma_ab_pv2(const float* __restrict__ A,
                                           const float* __restrict__ B, int ldb,
                                           float c[4][4][4]) {
    __shared__ float As[2][128][20];
    __shared__ float Bs[2][128][20];
    const int tid = threadIdx.x, lane = tid & 31, wid = tid >> 5;
    const int wm = (wid & 1) * 64, wn = (wid >> 1) * 32;
    const int lr = lane >> 2, lc = lane & 3;
    const int gr = tid >> 2, gc = (tid & 3) * 4;

    float4 pa[2];
    float pbv[8];
    auto ld = [&](int k0) {
        pa[0] = *(const float4*)(A + (size_t)gr * 1024 + k0 + gc);
        pa[1] = *(const float4*)(A + (size_t)(gr + 64) * 1024 + k0 + gc);
#pragma unroll
        for (int i = 0; i < 8; i++) {
            int li = tid + i * 256;            // 0..2047
            int k = li >> 7, n = li & 127;
            pbv[i] = B[(size_t)(k0 + k) * ldb + n];
        }
    };
    auto st = [&](int buf) {
        *(float4*)&As[buf][gr][gc]      = pa[0];
        *(float4*)&As[buf][gr + 64][gc] = pa[1];
#pragma unroll
        for (int i = 0; i < 8; i++) {
            int li = tid + i * 256;
            int k = li >> 7, n = li & 127;
            Bs[buf][n][k] = pbv[i];            // transpose to [n][k]
        }
    };

    ld(0); st(0);
    __syncthreads();
#pragma unroll 1
    for (int k0 = 0; k0 < 1024; k0 += 16) {
        const int cur = (k0 >> 4) & 1;
        const bool more = (k0 + 16) < 1024;
        if (more) ld(k0 + 16);
        stage_compute(As[cur], Bs[cur], wm, wn, lr, lc, c);
        if (more) {
            st(cur ^ 1);
            __syncthreads();
        }
    }
}

// ---------------- kernels ----------------

// qkv = x @ w_qkv^T ; scatter pre-rounded tf32 into g_q/g_k/g_v [B,H,N,HD]
__global__ void __launch_bounds__(256, 2)
k_qkv(const float* __restrict__ X, const float* __restrict__ W) {
    const int row0 = blockIdx.y * 128;   // b*N+n
    const int col0 = blockIdx.x * 128;   // 0..1535, one full head chunk
    float c[4][4][4] = {};
    mma_abt2<Cq, true, true>(X + (size_t)row0 * Cq, Cq, W + (size_t)col0 * Cq, Cq, c);

    const int part = col0 >> 9;
    const int h = (col0 & 511) >> 7;
    float* dst = (part == 0) ? g_q : (part == 1) ? g_k : g_v;

    const int tid = threadIdx.x, lane = tid & 31, wid = tid >> 5;
    const int wm = (wid & 1) * 64, wn = (wid >> 1) * 32;
    const int lr = lane >> 2, lc = lane & 3;
#pragma unroll
    for (int t = 0; t < 4; t++)
#pragma unroll
        for (int u = 0; u < 4; u++) {
            const int d = wn + u * 8 + 2 * lc;
#pragma unroll
            for (int half = 0; half < 2; half++) {
                const int r = row0 + wm + t * 16 + lr + half * 8;
                const int b = r >> 10, n = r & 1023;
                const size_t base = ((size_t)(b * Hq + h) * Nq + n) * HDq + d;
                dst[base]     = tfr(c[t][u][half * 2 + 0]);
                dst[base + 1] = tfr(c[t][u][half * 2 + 1]);
            }
        }
}

// S[z] = q[z] @ k[z]^T (raw; scale folded into mix)
__global__ void __launch_bounds__(256, 2) k_scores() {
    const int z = blockIdx.z;
    const int row0 = blockIdx.y * 128;
    const int col0 = blockIdx.x * 128;
    float c[4][4][4] = {};
    const float* A = g_q + (size_t)z * Nq * HDq + (size_t)row0 * HDq;
    const float* B = g_k + (size_t)z * Nq * HDq + (size_t)col0 * HDq;
    mma_abt2<HDq, false, false>(A, HDq, B, HDq, c);

    float* S = g_s + (size_t)z * Nq * Nq;
    const int tid = threadIdx.x, lane = tid & 31, wid = tid >> 5;
    const int wm = (wid & 1) * 64, wn = (wid >> 1) * 32;
    const int lr = lane >> 2, lc = lane & 3;
#pragma unroll
    for (int t = 0; t < 4; t++)
#pragma unroll
        for (int u = 0; u < 4; u++) {
            const int col = col0 + wn + u * 8 + 2 * lc;
#pragma unroll
            for (int half = 0; half < 2; half++) {
                const int r = row0 + wm + t * 16 + lr + half * 8;
                *(float2*)(S + (size_t)r * Nq + col) =
                    make_float2(c[t][u][half * 2 + 0], c[t][u][half * 2 + 1]);
            }
        }
}

__device__ __forceinline__ float bred(float v, bool is_max, float* red) {
#pragma unroll
    for (int o = 16; o > 0; o >>= 1) {
        float t = __shfl_xor_sync(0xffffffffu, v, o);
        v = is_max ? fmaxf(v, t) : (v + t);
    }
    const int tid = threadIdx.x;
    if ((tid & 31) == 0) red[tid >> 5] = v;
    __syncthreads();
    if (tid == 0) {
        float r = red[0];
        for (int w = 1; w < 8; w++) r = is_max ? fmaxf(r, red[w]) : (r + red[w]);
        red[0] = r;
    }
    __syncthreads();
    float r = red[0];
    __syncthreads();
    return r;
}

// per (b,n): mix heads with M*SCALE, softmax, write probs in place. Pure regs.
__global__ void __launch_bounds__(256) k_mix_softmax(const float* __restrict__ w_main,
                                                     const float* __restrict__ w_rest) {
    __shared__ float red[8];
    const int bn = blockIdx.x;
    const int b = bn >> 10, n = bn & 1023;
    const int tid = threadIdx.x;
    const int m0 = tid * 4;
    const size_t base = ((size_t)(b * Hq) * Nq + n) * Nq;
    const size_t hstride = (size_t)Nq * Nq;

    float4 sh[Hq];
#pragma unroll
    for (int h = 0; h < Hq; h++)
        sh[h] = *(const float4*)(g_s + base + (size_t)h * hstride + m0);

    float Mr[Hq][Hq];
#pragma unroll
    for (int i = 0; i < Hq; i++)
#pragma unroll
        for (int j = 0; j < Hq; j++) {
            float w = (j == i) ? w_main[i] : w_rest[i * (Hq - 1) + j - (j > i ? 1 : 0)];
            Mr[i][j] = w * SCALEq;
        }

#pragma unroll
    for (int i = 0; i < Hq; i++) {
        float v[4];
        v[0] = Mr[i][0] * sh[0].x + Mr[i][1] * sh[1].x + Mr[i][2] * sh[2].x + Mr[i][3] * sh[3].x;
        v[1] = Mr[i][0] * sh[0].y + Mr[i][1] * sh[1].y + Mr[i][2] * sh[2].y + Mr[i][3] * sh[3].y;
        v[2] = Mr[i][0] * sh[0].z + Mr[i][1] * sh[1].z + Mr[i][2] * sh[2].z + Mr[i][3] * sh[3].z;
        v[3] = Mr[i][0] * sh[0].w + Mr[i][1] * sh[1].w + Mr[i][2] * sh[2].w + Mr[i][3] * sh[3].w;
        float lmax = fmaxf(fmaxf(v[0], v[1]), fmaxf(v[2], v[3]));
        const float gmax = bred(lmax, true, red);
        float lsum = 0.f;
#pragma unroll
        for (int t = 0; t < 4; t++) { v[t] = __expf(v[t] - gmax); lsum += v[t]; }
        const float gsum = bred(lsum, false, red);
        const float inv = 1.f / gsum;
        float4 o = make_float4(tfr(v[0] * inv), tfr(v[1] * inv), tfr(v[2] * inv), tfr(v[3] * inv));
        *(float4*)(g_s + base + (size_t)i * hstride + m0) = o;
    }
}

// out[z] = P[z] @ V[z] -> g_y[b, n, h*HD + d] (tf32-rounded for proj)
__global__ void __launch_bounds__(256, 2) k_pv() {
    const int z = blockIdx.z;
    const int row0 = blockIdx.y * 128;  // n
    float c[4][4][4] = {};
    const float* A = g_s + (size_t)z * Nq * Nq + (size_t)row0 * Nq;
    const float* B = g_v + (size_t)z * Nq * HDq;
    mma_ab_pv2(A, B, HDq, c);

    const int b = z >> 2, h = z & 3;
    const int tid = threadIdx.x, lane = tid & 31, wid = tid >> 5;
    const int wm = (wid & 1) * 64, wn = (wid >> 1) * 32;
    const int lr = lane >> 2, lc = lane & 3;
#pragma unroll
    for (int t = 0; t < 4; t++)
#pragma unroll
        for (int u = 0; u < 4; u++) {
            const int d = wn + u * 8 + 2 * lc;
#pragma unroll
            for (int half = 0; half < 2; half++) {
                const int n = row0 + wm + t * 16 + lr + half * 8;
                const size_t base = ((size_t)b * Nq + n) * Cq + h * HDq + d;
                g_y[base]     = tfr(c[t][u][half * 2 + 0]);
                g_y[base + 1] = tfr(c[t][u][half * 2 + 1]);
            }
        }
}

// out = y @ w_proj^T + b_proj
__global__ void __launch_bounds__(256, 2)
k_proj(const float* __restrict__ Wp, const float* __restrict__ bias,
       float* __restrict__ out) {
    const int row0 = blockIdx.y * 128;
    const int col0 = blockIdx.x * 128;
    float c[4][4][4] = {};
    mma_abt2<Cq, false, true>(g_y + (size_t)row0 * Cq, Cq, Wp + (size_t)col0 * Cq, Cq, c);

    const int tid = threadIdx.x, lane = tid & 31, wid = tid >> 5;
    const int wm = (wid & 1) * 64, wn = (wid >> 1) * 32;
    const int lr = lane >> 2, lc = lane & 3;
#pragma unroll
    for (int t = 0; t < 4; t++)
#pragma unroll
        for (int u = 0; u < 4; u++) {
            const int col = col0 + wn + u * 8 + 2 * lc;
            const float b0 = bias[col], b1 = bias[col + 1];
#pragma unroll
            for (int half = 0; half < 2; half++) {
                const int r = row0 + wm + t * 16 + lr + half * 8;
                *(float2*)(out + (size_t)r * Cq + col) =
                    make_float2(c[t][u][half * 2 + 0] + b0, c[t][u][half * 2 + 1] + b1);
            }
        }
}

// ---------------- launch ----------------
extern "C" void kernel_launch(void* const* d_in, const int* in_sizes, int n_in,
                              void* d_out, int out_size) {
    const float* x      = (const float*)d_in[0];
    const float* w_qkv  = (const float*)d_in[1];
    const float* w_proj = (const float*)d_in[2];
    const float* b_proj = (const float*)d_in[3];
    const float* w_main = (const float*)d_in[4];
    const float* w_rest = (const float*)d_in[5];
    float* out = (float*)d_out;

    dim3 blk(256);
    k_qkv<<<dim3(1536 / 128, (Bq * Nq) / 128), blk>>>(x, w_qkv);
    k_scores<<<dim3(Nq / 128, Nq / 128, Bq * Hq), blk>>>();
    k_mix_softmax<<<Bq * Nq, blk>>>(w_main, w_rest);
    k_pv<<<dim3(1, Nq / 128, Bq * Hq), blk>>>();
    k_proj<<<dim3(Cq / 128, (Bq * Nq) / 128), blk>>>(w_proj, b_proj, out);
}

// round 7
// speedup vs baseline: 1.4824x; 1.4824x over previous
#include <cuda_runtime.h>
#include <math.h>
#include <stdint.h>

#define Bq 8
#define Nq 1024
#define Cq 512
#define Hq 4
#define HDq 128
#define SCALEq 0.08838834764831845f

// ---------------- scratch ----------------
__device__ float g_q[Bq * Hq * Nq * HDq];
__device__ float g_k[Bq * Hq * Nq * HDq];
__device__ float g_v[Bq * Hq * Nq * HDq];
__device__ float g_s[(size_t)Bq * Hq * Nq * Nq];
__device__ float g_y[Bq * Nq * Cq];
__device__ float g_x[Bq * Nq * Cq];      // tf32-rounded x
__device__ float g_wq[3 * Cq * Cq];      // tf32-rounded w_qkv
__device__ float g_wp[Cq * Cq];          // tf32-rounded w_proj

// ---------------- tf32 helpers ----------------
__device__ __forceinline__ unsigned f2tf(float f) {
    unsigned r;
    asm("cvt.rna.tf32.f32 %0, %1;" : "=r"(r) : "f"(f));
    return r;
}
__device__ __forceinline__ float tfr(float f) { return __uint_as_float(f2tf(f)); }

__device__ __forceinline__ void mma8(float c[4], const unsigned a[4], const unsigned b[2]) {
    asm volatile(
        "mma.sync.aligned.m16n8k8.row.col.f32.tf32.tf32.f32 "
        "{%0,%1,%2,%3},{%4,%5,%6,%7},{%8,%9},{%0,%1,%2,%3};"
        : "+f"(c[0]), "+f"(c[1]), "+f"(c[2]), "+f"(c[3])
        : "r"(a[0]), "r"(a[1]), "r"(a[2]), "r"(a[3]), "r"(b[0]), "r"(b[1]));
}

// ---------------- cp.async ----------------
__device__ __forceinline__ void cpa16(uint32_t dst, const void* src) {
    asm volatile("cp.async.ca.shared.global [%0], [%1], 16;" :: "r"(dst), "l"(src));
}
#define CP_COMMIT() asm volatile("cp.async.commit_group;")
#define CP_WAIT(n)  asm volatile("cp.async.wait_group %0;" :: "n"(n))

// ---------------- fragment compute ----------------
// As [row][k] stride 20, Bs [n][k] stride 20 (abt layout)
__device__ __forceinline__ void stage_abt(const float (*As)[20], const float (*Bs)[20],
                                          int wm, int wn, int lr, int lc,
                                          float c[4][4][4]) {
#pragma unroll
    for (int kk = 0; kk < 16; kk += 8) {
        unsigned a[4][4], b[4][2];
#pragma unroll
        for (int t = 0; t < 4; t++) {
            a[t][0] = __float_as_uint(As[wm + t * 16 + lr][kk + lc]);
            a[t][1] = __float_as_uint(As[wm + t * 16 + 8 + lr][kk + lc]);
            a[t][2] = __float_as_uint(As[wm + t * 16 + lr][kk + lc + 4]);
            a[t][3] = __float_as_uint(As[wm + t * 16 + 8 + lr][kk + lc + 4]);
        }
#pragma unroll
        for (int u = 0; u < 4; u++) {
            b[u][0] = __float_as_uint(Bs[wn + u * 8 + lr][kk + lc]);
            b[u][1] = __float_as_uint(Bs[wn + u * 8 + lr][kk + lc + 4]);
        }
#pragma unroll
        for (int t = 0; t < 4; t++)
#pragma unroll
            for (int u = 0; u < 4; u++) mma8(c[t][u], a[t], b[u]);
    }
}

// As [row][k] stride 20, Bs [k][n] stride 72 (pv layout, untransposed)
__device__ __forceinline__ void stage_pv(const float (*As)[20], const float (*Bs)[72],
                                         int wm, int wn, int lr, int lc,
                                         float c[4][4][4]) {
#pragma unroll
    for (int kk = 0; kk < 16; kk += 8) {
        unsigned a[4][4], b[4][2];
#pragma unroll
        for (int t = 0; t < 4; t++) {
            a[t][0] = __float_as_uint(As[wm + t * 16 + lr][kk + lc]);
            a[t][1] = __float_as_uint(As[wm + t * 16 + 8 + lr][kk + lc]);
            a[t][2] = __float_as_uint(As[wm + t * 16 + lr][kk + lc + 4]);
            a[t][3] = __float_as_uint(As[wm + t * 16 + 8 + lr][kk + lc + 4]);
        }
#pragma unroll
        for (int u = 0; u < 4; u++) {
            b[u][0] = __float_as_uint(Bs[kk + lc][wn + u * 8 + lr]);
            b[u][1] = __float_as_uint(Bs[kk + lc + 4][wn + u * 8 + lr]);
        }
#pragma unroll
        for (int t = 0; t < 4; t++)
#pragma unroll
            for (int u = 0; u < 4; u++) mma8(c[t][u], a[t], b[u]);
    }
}

// ===== core: C(128x64) = A(128xK) * B(64xK)^T, 128 thr, 3-stage cp.async =====
template <int K>
__device__ __forceinline__ void mma_abt3(const float* __restrict__ A, int lda,
                                         const float* __restrict__ B, int ldb,
                                         float c[4][4][4]) {
    __shared__ float As[3][128][20];
    __shared__ float Bs[3][64][20];
    const int tid = threadIdx.x, lane = tid & 31, wid = tid >> 5;
    const int wm = (wid >> 1) * 64, wn = (wid & 1) * 32;
    const int lr = lane >> 2, lc = lane & 3;
    const int ar = tid >> 2, ac = (tid & 3) * 4;   // 32 rows per pass

    auto issue = [&](int s, int k0) {
        uint32_t bA = (uint32_t)__cvta_generic_to_shared(&As[s][0][0]);
        uint32_t bB = (uint32_t)__cvta_generic_to_shared(&Bs[s][0][0]);
#pragma unroll
        for (int i = 0; i < 4; i++) {
            int r = ar + i * 32;
            cpa16(bA + (r * 20 + ac) * 4, A + (size_t)r * lda + k0 + ac);
        }
#pragma unroll
        for (int i = 0; i < 2; i++) {
            int r = ar + i * 32;
            cpa16(bB + (r * 20 + ac) * 4, B + (size_t)r * ldb + k0 + ac);
        }
        CP_COMMIT();
    };

    constexpr int NS = K / 16;
    issue(0, 0);
    issue(1, 16);
#pragma unroll 1
    for (int s = 0; s < NS; s++) {
        if (s + 1 < NS) { CP_WAIT(1); } else { CP_WAIT(0); }
        __syncthreads();
        if (s + 2 < NS) issue((s + 2) % 3, (s + 2) * 16);
        stage_abt(As[s % 3], Bs[s % 3], wm, wn, lr, lc, c);
        __syncthreads();
    }
}

// ===== core: C(128x64) = A(128x1024) * B(1024x64slice), B row-major [k][128] ===
__device__ __forceinline__ void mma_pv3(const float* __restrict__ A,
                                        const float* __restrict__ B,   // + d-col offset
                                        float c[4][4][4]) {
    __shared__ float As[3][128][20];
    __shared__ float Bs[3][16][72];
    const int tid = threadIdx.x, lane = tid & 31, wid = tid >> 5;
    const int wm = (wid >> 1) * 64, wn = (wid & 1) * 32;
    const int lr = lane >> 2, lc = lane & 3;
    const int ar = tid >> 2, ac = (tid & 3) * 4;
    const int bkr = tid >> 4, bkc = (tid & 15) * 4;   // B: 8 k-rows per pass, 16 chunks/row... (row=tid/16, col=(tid%16)*4)

    auto issue = [&](int s, int k0) {
        uint32_t bA = (uint32_t)__cvta_generic_to_shared(&As[s][0][0]);
        uint32_t bB = (uint32_t)__cvta_generic_to_shared(&Bs[s][0][0]);
#pragma unroll
        for (int i = 0; i < 4; i++) {
            int r = ar + i * 32;
            cpa16(bA + (r * 20 + ac) * 4, A + (size_t)r * 1024 + k0 + ac);
        }
        // B tile: 16 k-rows x 64 d floats = 256 chunks; 128 thr -> 2 each
#pragma unroll
        for (int i = 0; i < 2; i++) {
            int k = bkr + i * 8;
            cpa16(bB + (k * 72 + bkc) * 4, B + (size_t)(k0 + k) * HDq + bkc);
        }
        CP_COMMIT();
    };

    constexpr int NS = 1024 / 16;
    issue(0, 0);
    issue(1, 16);
#pragma unroll 1
    for (int s = 0; s < NS; s++) {
        if (s + 1 < NS) { CP_WAIT(1); } else { CP_WAIT(0); }
        __syncthreads();
        if (s + 2 < NS) issue((s + 2) % 3, (s + 2) * 16);
        stage_pv(As[s % 3], Bs[s % 3], wm, wn, lr, lc, c);
        __syncthreads();
    }
}

// ---------------- kernels ----------------

// tf32 pre-round pass (float4 grid-stride)
__global__ void k_round(const float* __restrict__ src, float* __restrict__ dst, int n4) {
    int i = blockIdx.x * blockDim.x + threadIdx.x;
    if (i >= n4) return;
    float4 v = ((const float4*)src)[i];
    v.x = tfr(v.x); v.y = tfr(v.y); v.z = tfr(v.z); v.w = tfr(v.w);
    ((float4*)dst)[i] = v;
}

// qkv = x @ w_qkv^T ; scatter tf32-rounded into g_q/g_k/g_v [B,H,N,HD]
__global__ void __launch_bounds__(128, 4) k_qkv() {
    const int row0 = blockIdx.y * 128;
    const int col0 = blockIdx.x * 64;
    float c[4][4][4] = {};
    mma_abt3<Cq>(g_x + (size_t)row0 * Cq, Cq, g_wq + (size_t)col0 * Cq, Cq, c);

    const int part = col0 >> 9;
    const int h = (col0 & 511) >> 7;
    const int d0 = col0 & 127;
    float* dst = (part == 0) ? g_q : (part == 1) ? g_k : g_v;

    const int tid = threadIdx.x, lane = tid & 31, wid = tid >> 5;
    const int wm = (wid >> 1) * 64, wn = (wid & 1) * 32;
    const int lr = lane >> 2, lc = lane & 3;
#pragma unroll
    for (int t = 0; t < 4; t++)
#pragma unroll
        for (int u = 0; u < 4; u++) {
            const int d = d0 + wn + u * 8 + 2 * lc;
#pragma unroll
            for (int half = 0; half < 2; half++) {
                const int r = row0 + wm + t * 16 + lr + half * 8;
                const int b = r >> 10, n = r & 1023;
                const size_t base = ((size_t)(b * Hq + h) * Nq + n) * HDq + d;
                dst[base]     = tfr(c[t][u][half * 2 + 0]);
                dst[base + 1] = tfr(c[t][u][half * 2 + 1]);
            }
        }
}

// S[z] = q[z] @ k[z]^T (raw; scale folded into mix)
__global__ void __launch_bounds__(128, 4) k_scores() {
    const int z = blockIdx.z;
    const int row0 = blockIdx.y * 128;
    const int col0 = blockIdx.x * 64;
    float c[4][4][4] = {};
    const float* A = g_q + (size_t)z * Nq * HDq + (size_t)row0 * HDq;
    const float* B = g_k + (size_t)z * Nq * HDq + (size_t)col0 * HDq;
    mma_abt3<HDq>(A, HDq, B, HDq, c);

    float* S = g_s + (size_t)z * Nq * Nq;
    const int tid = threadIdx.x, lane = tid & 31, wid = tid >> 5;
    const int wm = (wid >> 1) * 64, wn = (wid & 1) * 32;
    const int lr = lane >> 2, lc = lane & 3;
#pragma unroll
    for (int t = 0; t < 4; t++)
#pragma unroll
        for (int u = 0; u < 4; u++) {
            const int col = col0 + wn + u * 8 + 2 * lc;
#pragma unroll
            for (int half = 0; half < 2; half++) {
                const int r = row0 + wm + t * 16 + lr + half * 8;
                *(float2*)(S + (size_t)r * Nq + col) =
                    make_float2(c[t][u][half * 2 + 0], c[t][u][half * 2 + 1]);
            }
        }
}

__device__ __forceinline__ float bred(float v, bool is_max, float* red) {
#pragma unroll
    for (int o = 16; o > 0; o >>= 1) {
        float t = __shfl_xor_sync(0xffffffffu, v, o);
        v = is_max ? fmaxf(v, t) : (v + t);
    }
    const int tid = threadIdx.x;
    if ((tid & 31) == 0) red[tid >> 5] = v;
    __syncthreads();
    if (tid == 0) {
        float r = red[0];
        for (int w = 1; w < 8; w++) r = is_max ? fmaxf(r, red[w]) : (r + red[w]);
        red[0] = r;
    }
    __syncthreads();
    float r = red[0];
    __syncthreads();
    return r;
}

// per (b,n): mix heads with M*SCALE, softmax, write probs in place. Pure regs.
__global__ void __launch_bounds__(256) k_mix_softmax(const float* __restrict__ w_main,
                                                     const float* __restrict__ w_rest) {
    __shared__ float red[8];
    const int bn = blockIdx.x;
    const int b = bn >> 10, n = bn & 1023;
    const int tid = threadIdx.x;
    const int m0 = tid * 4;
    const size_t base = ((size_t)(b * Hq) * Nq + n) * Nq;
    const size_t hstride = (size_t)Nq * Nq;

    float4 sh[Hq];
#pragma unroll
    for (int h = 0; h < Hq; h++)
        sh[h] = *(const float4*)(g_s + base + (size_t)h * hstride + m0);

    float Mr[Hq][Hq];
#pragma unroll
    for (int i = 0; i < Hq; i++)
#pragma unroll
        for (int j = 0; j < Hq; j++) {
            float w = (j == i) ? w_main[i] : w_rest[i * (Hq - 1) + j - (j > i ? 1 : 0)];
            Mr[i][j] = w * SCALEq;
        }

#pragma unroll
    for (int i = 0; i < Hq; i++) {
        float v[4];
        v[0] = Mr[i][0] * sh[0].x + Mr[i][1] * sh[1].x + Mr[i][2] * sh[2].x + Mr[i][3] * sh[3].x;
        v[1] = Mr[i][0] * sh[0].y + Mr[i][1] * sh[1].y + Mr[i][2] * sh[2].y + Mr[i][3] * sh[3].y;
        v[2] = Mr[i][0] * sh[0].z + Mr[i][1] * sh[1].z + Mr[i][2] * sh[2].z + Mr[i][3] * sh[3].z;
        v[3] = Mr[i][0] * sh[0].w + Mr[i][1] * sh[1].w + Mr[i][2] * sh[2].w + Mr[i][3] * sh[3].w;
        float lmax = fmaxf(fmaxf(v[0], v[1]), fmaxf(v[2], v[3]));
        const float gmax = bred(lmax, true, red);
        float lsum = 0.f;
#pragma unroll
        for (int t = 0; t < 4; t++) { v[t] = __expf(v[t] - gmax); lsum += v[t]; }
        const float gsum = bred(lsum, false, red);
        const float inv = 1.f / gsum;
        float4 o = make_float4(tfr(v[0] * inv), tfr(v[1] * inv), tfr(v[2] * inv), tfr(v[3] * inv));
        *(float4*)(g_s + base + (size_t)i * hstride + m0) = o;
    }
}

// out[z] = P[z] @ V[z] -> g_y[b, n, h*HD + d] (tf32-rounded for proj)
__global__ void __launch_bounds__(128, 4) k_pv() {
    const int z = blockIdx.z;
    const int row0 = blockIdx.y * 128;  // n
    const int col0 = blockIdx.x * 64;   // d
    float c[4][4][4] = {};
    const float* A = g_s + (size_t)z * Nq * Nq + (size_t)row0 * Nq;
    const float* B = g_v + (size_t)z * Nq * HDq + col0;
    mma_pv3(A, B, c);

    const int b = z >> 2, h = z & 3;
    const int tid = threadIdx.x, lane = tid & 31, wid = tid >> 5;
    const int wm = (wid >> 1) * 64, wn = (wid & 1) * 32;
    const int lr = lane >> 2, lc = lane & 3;
#pragma unroll
    for (int t = 0; t < 4; t++)
#pragma unroll
        for (int u = 0; u < 4; u++) {
            const int d = col0 + wn + u * 8 + 2 * lc;
#pragma unroll
            for (int half = 0; half < 2; half++) {
                const int n = row0 + wm + t * 16 + lr + half * 8;
                const size_t base = ((size_t)b * Nq + n) * Cq + h * HDq + d;
                g_y[base]     = tfr(c[t][u][half * 2 + 0]);
                g_y[base + 1] = tfr(c[t][u][half * 2 + 1]);
            }
        }
}

// out = y @ w_proj^T + b_proj
__global__ void __launch_bounds__(128, 4)
k_proj(const float* __restrict__ bias, float* __restrict__ out) {
    const int row0 = blockIdx.y * 128;
    const int col0 = blockIdx.x * 64;
    float c[4][4][4] = {};
    mma_abt3<Cq>(g_y + (size_t)row0 * Cq, Cq, g_wp + (size_t)col0 * Cq, Cq, c);

    const int tid = threadIdx.x, lane = tid & 31, wid = tid >> 5;
    const int wm = (wid >> 1) * 64, wn = (wid & 1) * 32;
    const int lr = lane >> 2, lc = lane & 3;
#pragma unroll
    for (int t = 0; t < 4; t++)
#pragma unroll
        for (int u = 0; u < 4; u++) {
            const int col = col0 + wn + u * 8 + 2 * lc;
            const float b0 = bias[col], b1 = bias[col + 1];
#pragma unroll
            for (int half = 0; half < 2; half++) {
                const int r = row0 + wm + t * 16 + lr + half * 8;
                *(float2*)(out + (size_t)r * Cq + col) =
                    make_float2(c[t][u][half * 2 + 0] + b0, c[t][u][half * 2 + 1] + b1);
            }
        }
}

// ---------------- launch ----------------
extern "C" void kernel_launch(void* const* d_in, const int* in_sizes, int n_in,
                              void* d_out, int out_size) {
    const float* x      = (const float*)d_in[0];
    const float* w_qkv  = (const float*)d_in[1];
    const float* w_proj = (const float*)d_in[2];
    const float* b_proj = (const float*)d_in[3];
    const float* w_main = (const float*)d_in[4];
    const float* w_rest = (const float*)d_in[5];
    float* out = (float*)d_out;

    float* p_x;  cudaGetSymbolAddress((void**)&p_x,  g_x);
    float* p_wq; cudaGetSymbolAddress((void**)&p_wq, g_wq);
    float* p_wp; cudaGetSymbolAddress((void**)&p_wp, g_wp);

    dim3 blk(128);
    {
        int n4 = Bq * Nq * Cq / 4;
        k_round<<<(n4 + 255) / 256, 256>>>(x, p_x, n4);
        n4 = 3 * Cq * Cq / 4;
        k_round<<<(n4 + 255) / 256, 256>>>(w_qkv, p_wq, n4);
        n4 = Cq * Cq / 4;
        k_round<<<(n4 + 255) / 256, 256>>>(w_proj, p_wp, n4);
    }
    k_qkv<<<dim3(1536 / 64, (Bq * Nq) / 128), blk>>>();
    k_scores<<<dim3(Nq / 64, Nq / 128, Bq * Hq), blk>>>();
    k_mix_softmax<<<Bq * Nq, dim3(256)>>>(w_main, w_rest);
    k_pv<<<dim3(HDq / 64, Nq / 128, Bq * Hq), blk>>>();
    k_proj<<<dim3(Cq / 64, (Bq * Nq) / 128), blk>>>(b_proj, out);
}

// round 8
// speedup vs baseline: 1.7492x; 1.1799x over previous
#include <cuda_runtime.h>
#include <math.h>
#include <stdint.h>

#define Bq 8
#define Nq 1024
#define Cq 512
#define Hq 4
#define HDq 128
#define SCALEq 0.08838834764831845f

// ---------------- scratch ----------------
__device__ float g_q[Bq * Hq * Nq * HDq];
__device__ float g_k[Bq * Hq * Nq * HDq];
__device__ float g_v[Bq * Hq * Nq * HDq];
__device__ float g_s[(size_t)Bq * Hq * Nq * Nq];
__device__ float g_y[Bq * Nq * Cq];
__device__ float g_x[Bq * Nq * Cq];      // tf32-rounded x
__device__ float g_wq[3 * Cq * Cq];      // tf32-rounded w_qkv
__device__ float g_wp[Cq * Cq];          // tf32-rounded w_proj

// ---------------- tf32 helpers ----------------
__device__ __forceinline__ unsigned f2tf(float f) {
    unsigned r;
    asm("cvt.rna.tf32.f32 %0, %1;" : "=r"(r) : "f"(f));
    return r;
}
__device__ __forceinline__ float tfr(float f) { return __uint_as_float(f2tf(f)); }

__device__ __forceinline__ void mma8(float c[4], const unsigned a[4], const unsigned b[2]) {
    asm volatile(
        "mma.sync.aligned.m16n8k8.row.col.f32.tf32.tf32.f32 "
        "{%0,%1,%2,%3},{%4,%5,%6,%7},{%8,%9},{%0,%1,%2,%3};"
        : "+f"(c[0]), "+f"(c[1]), "+f"(c[2]), "+f"(c[3])
        : "r"(a[0]), "r"(a[1]), "r"(a[2]), "r"(a[3]), "r"(b[0]), "r"(b[1]));
}

// ---------------- cp.async ----------------
__device__ __forceinline__ void cpa16(uint32_t dst, const void* src) {
    asm volatile("cp.async.ca.shared.global [%0], [%1], 16;" :: "r"(dst), "l"(src));
}
#define CP_COMMIT() asm volatile("cp.async.commit_group;")
#define CP_WAIT(n)  asm volatile("cp.async.wait_group %0;" :: "n"(n))

// ---------------- fragment compute, 64x64 warp tile ----------------
// As [row][k] stride 20, Bs [n][k] stride 20
__device__ __forceinline__ void stage_abt64(const float (*As)[20], const float (*Bs)[20],
                                            int wm, int wn, int lr, int lc,
                                            float c[4][8][4]) {
#pragma unroll
    for (int kk = 0; kk < 16; kk += 8) {
        unsigned b[8][2];
#pragma unroll
        for (int u = 0; u < 8; u++) {
            b[u][0] = __float_as_uint(Bs[wn + u * 8 + lr][kk + lc]);
            b[u][1] = __float_as_uint(Bs[wn + u * 8 + lr][kk + lc + 4]);
        }
#pragma unroll
        for (int t = 0; t < 4; t++) {
            unsigned a[4];
            a[0] = __float_as_uint(As[wm + t * 16 + lr][kk + lc]);
            a[1] = __float_as_uint(As[wm + t * 16 + 8 + lr][kk + lc]);
            a[2] = __float_as_uint(As[wm + t * 16 + lr][kk + lc + 4]);
            a[3] = __float_as_uint(As[wm + t * 16 + 8 + lr][kk + lc + 4]);
#pragma unroll
            for (int u = 0; u < 8; u++) mma8(c[t][u], a, b[u]);
        }
    }
}

// As [row][k] stride 20, Bs [k][n] stride 136
__device__ __forceinline__ void stage_pv64(const float (*As)[20], const float (*Bs)[136],
                                           int wm, int wn, int lr, int lc,
                                           float c[4][8][4]) {
#pragma unroll
    for (int kk = 0; kk < 16; kk += 8) {
        unsigned b[8][2];
#pragma unroll
        for (int u = 0; u < 8; u++) {
            b[u][0] = __float_as_uint(Bs[kk + lc][wn + u * 8 + lr]);
            b[u][1] = __float_as_uint(Bs[kk + lc + 4][wn + u * 8 + lr]);
        }
#pragma unroll
        for (int t = 0; t < 4; t++) {
            unsigned a[4];
            a[0] = __float_as_uint(As[wm + t * 16 + lr][kk + lc]);
            a[1] = __float_as_uint(As[wm + t * 16 + 8 + lr][kk + lc]);
            a[2] = __float_as_uint(As[wm + t * 16 + lr][kk + lc + 4]);
            a[3] = __float_as_uint(As[wm + t * 16 + 8 + lr][kk + lc + 4]);
#pragma unroll
            for (int u = 0; u < 8; u++) mma8(c[t][u], a, b[u]);
        }
    }
}

// ===== core: C(128x128) = A(128xK) * B(128xK)^T, 128 thr, 3-stage, 1 sync ====
template <int K>
__device__ __forceinline__ void mma_abt64(const float* __restrict__ A, int lda,
                                          const float* __restrict__ B, int ldb,
                                          float c[4][8][4]) {
    __shared__ __align__(16) float As[3][128][20];
    __shared__ __align__(16) float Bs[3][128][20];
    const int tid = threadIdx.x, lane = tid & 31, wid = tid >> 5;
    const int wm = (wid & 1) * 64, wn = (wid >> 1) * 64;
    const int lr = lane >> 2, lc = lane & 3;
    const int ar = tid >> 2, ac = (tid & 3) * 4;

    auto issue = [&](int s, int k0) {
        uint32_t bA = (uint32_t)__cvta_generic_to_shared(&As[s][0][0]);
        uint32_t bB = (uint32_t)__cvta_generic_to_shared(&Bs[s][0][0]);
#pragma unroll
        for (int i = 0; i < 4; i++) {
            int r = ar + i * 32;
            cpa16(bA + (r * 20 + ac) * 4, A + (size_t)r * lda + k0 + ac);
            cpa16(bB + (r * 20 + ac) * 4, B + (size_t)r * ldb + k0 + ac);
        }
        CP_COMMIT();
    };

    constexpr int NS = K / 16;
    issue(0, 0);
    issue(1, 16);
#pragma unroll 1
    for (int s = 0; s < NS; s++) {
        if (s + 1 < NS) { CP_WAIT(1); } else { CP_WAIT(0); }
        __syncthreads();
        if (s + 2 < NS) issue((s + 2) % 3, (s + 2) * 16);
        stage_abt64(As[s % 3], Bs[s % 3], wm, wn, lr, lc, c);
    }
}

// ===== core: C(128x128) = A(128x1024) * B(1024x128), B row-major [k][128] =====
__device__ __forceinline__ void mma_pv64(const float* __restrict__ A,
                                         const float* __restrict__ B,
                                         float c[4][8][4]) {
    __shared__ __align__(16) float As[3][128][20];
    __shared__ __align__(16) float Bs[3][16][136];
    const int tid = threadIdx.x, lane = tid & 31, wid = tid >> 5;
    const int wm = (wid & 1) * 64, wn = (wid >> 1) * 64;
    const int lr = lane >> 2, lc = lane & 3;
    const int ar = tid >> 2, ac = (tid & 3) * 4;

    auto issue = [&](int s, int k0) {
        uint32_t bA = (uint32_t)__cvta_generic_to_shared(&As[s][0][0]);
        uint32_t bB = (uint32_t)__cvta_generic_to_shared(&Bs[s][0][0]);
#pragma unroll
        for (int i = 0; i < 4; i++) {
            int r = ar + i * 32;
            cpa16(bA + (r * 20 + ac) * 4, A + (size_t)r * 1024 + k0 + ac);
        }
        // B tile: 16 k-rows x 128 d = 512 float4 chunks; 128 thr -> 4 each
#pragma unroll
        for (int i = 0; i < 4; i++) {
            int ch = tid + i * 128;
            int k = ch >> 5, d4 = (ch & 31) * 4;
            cpa16(bB + (k * 136 + d4) * 4, B + (size_t)(k0 + k) * HDq + d4);
        }
        CP_COMMIT();
    };

    constexpr int NS = 1024 / 16;
    issue(0, 0);
    issue(1, 16);
#pragma unroll 1
    for (int s = 0; s < NS; s++) {
        if (s + 1 < NS) { CP_WAIT(1); } else { CP_WAIT(0); }
        __syncthreads();
        if (s + 2 < NS) issue((s + 2) % 3, (s + 2) * 16);
        stage_pv64(As[s % 3], Bs[s % 3], wm, wn, lr, lc, c);
    }
}

// ---------------- kernels ----------------

__global__ void k_round(const float* __restrict__ src, float* __restrict__ dst, int n4) {
    int i = blockIdx.x * blockDim.x + threadIdx.x;
    if (i >= n4) return;
    float4 v = ((const float4*)src)[i];
    v.x = tfr(v.x); v.y = tfr(v.y); v.z = tfr(v.z); v.w = tfr(v.w);
    ((float4*)dst)[i] = v;
}

// qkv = x @ w_qkv^T ; scatter tf32-rounded into g_q/g_k/g_v [B,H,N,HD]
__global__ void __launch_bounds__(128, 2) k_qkv() {
    const int row0 = blockIdx.y * 128;
    const int col0 = blockIdx.x * 128;   // exactly one (part, head) chunk
    float c[4][8][4] = {};
    mma_abt64<Cq>(g_x + (size_t)row0 * Cq, Cq, g_wq + (size_t)col0 * Cq, Cq, c);

    const int part = col0 >> 9;
    const int h = (col0 & 511) >> 7;
    float* dst = (part == 0) ? g_q : (part == 1) ? g_k : g_v;

    const int tid = threadIdx.x, lane = tid & 31, wid = tid >> 5;
    const int wm = (wid & 1) * 64, wn = (wid >> 1) * 64;
    const int lr = lane >> 2, lc = lane & 3;
#pragma unroll
    for (int t = 0; t < 4; t++)
#pragma unroll
        for (int u = 0; u < 8; u++) {
            const int d = wn + u * 8 + 2 * lc;
#pragma unroll
            for (int half = 0; half < 2; half++) {
                const int r = row0 + wm + t * 16 + lr + half * 8;
                const int b = r >> 10, n = r & 1023;
                const size_t base = ((size_t)(b * Hq + h) * Nq + n) * HDq + d;
                dst[base]     = tfr(c[t][u][half * 2 + 0]);
                dst[base + 1] = tfr(c[t][u][half * 2 + 1]);
            }
        }
}

// S[z] = q[z] @ k[z]^T (raw; scale folded into mix)
__global__ void __launch_bounds__(128, 2) k_scores() {
    const int z = blockIdx.z;
    const int row0 = blockIdx.y * 128;
    const int col0 = blockIdx.x * 128;
    float c[4][8][4] = {};
    const float* A = g_q + (size_t)z * Nq * HDq + (size_t)row0 * HDq;
    const float* B = g_k + (size_t)z * Nq * HDq + (size_t)col0 * HDq;
    mma_abt64<HDq>(A, HDq, B, HDq, c);

    float* S = g_s + (size_t)z * Nq * Nq;
    const int tid = threadIdx.x, lane = tid & 31, wid = tid >> 5;
    const int wm = (wid & 1) * 64, wn = (wid >> 1) * 64;
    const int lr = lane >> 2, lc = lane & 3;
#pragma unroll
    for (int t = 0; t < 4; t++)
#pragma unroll
        for (int u = 0; u < 8; u++) {
            const int col = col0 + wn + u * 8 + 2 * lc;
#pragma unroll
            for (int half = 0; half < 2; half++) {
                const int r = row0 + wm + t * 16 + lr + half * 8;
                *(float2*)(S + (size_t)r * Nq + col) =
                    make_float2(c[t][u][half * 2 + 0], c[t][u][half * 2 + 1]);
            }
        }
}

__device__ __forceinline__ float bred(float v, bool is_max, float* red) {
#pragma unroll
    for (int o = 16; o > 0; o >>= 1) {
        float t = __shfl_xor_sync(0xffffffffu, v, o);
        v = is_max ? fmaxf(v, t) : (v + t);
    }
    const int tid = threadIdx.x;
    if ((tid & 31) == 0) red[tid >> 5] = v;
    __syncthreads();
    if (tid == 0) {
        float r = red[0];
        for (int w = 1; w < 8; w++) r = is_max ? fmaxf(r, red[w]) : (r + red[w]);
        red[0] = r;
    }
    __syncthreads();
    float r = red[0];
    __syncthreads();
    return r;
}

// per (b,n): mix heads with M*SCALE, softmax, write probs in place. Pure regs.
__global__ void __launch_bounds__(256) k_mix_softmax(const float* __restrict__ w_main,
                                                     const float* __restrict__ w_rest) {
    __shared__ float red[8];
    const int bn = blockIdx.x;
    const int b = bn >> 10, n = bn & 1023;
    const int tid = threadIdx.x;
    const int m0 = tid * 4;
    const size_t base = ((size_t)(b * Hq) * Nq + n) * Nq;
    const size_t hstride = (size_t)Nq * Nq;

    float4 sh[Hq];
#pragma unroll
    for (int h = 0; h < Hq; h++)
        sh[h] = *(const float4*)(g_s + base + (size_t)h * hstride + m0);

    float Mr[Hq][Hq];
#pragma unroll
    for (int i = 0; i < Hq; i++)
#pragma unroll
        for (int j = 0; j < Hq; j++) {
            float w = (j == i) ? w_main[i] : w_rest[i * (Hq - 1) + j - (j > i ? 1 : 0)];
            Mr[i][j] = w * SCALEq;
        }

#pragma unroll
    for (int i = 0; i < Hq; i++) {
        float v[4];
        v[0] = Mr[i][0] * sh[0].x + Mr[i][1] * sh[1].x + Mr[i][2] * sh[2].x + Mr[i][3] * sh[3].x;
        v[1] = Mr[i][0] * sh[0].y + Mr[i][1] * sh[1].y + Mr[i][2] * sh[2].y + Mr[i][3] * sh[3].y;
        v[2] = Mr[i][0] * sh[0].z + Mr[i][1] * sh[1].z + Mr[i][2] * sh[2].z + Mr[i][3] * sh[3].z;
        v[3] = Mr[i][0] * sh[0].w + Mr[i][1] * sh[1].w + Mr[i][2] * sh[2].w + Mr[i][3] * sh[3].w;
        float lmax = fmaxf(fmaxf(v[0], v[1]), fmaxf(v[2], v[3]));
        const float gmax = bred(lmax, true, red);
        float lsum = 0.f;
#pragma unroll
        for (int t = 0; t < 4; t++) { v[t] = __expf(v[t] - gmax); lsum += v[t]; }
        const float gsum = bred(lsum, false, red);
        const float inv = 1.f / gsum;
        float4 o = make_float4(tfr(v[0] * inv), tfr(v[1] * inv), tfr(v[2] * inv), tfr(v[3] * inv));
        *(float4*)(g_s + base + (size_t)i * hstride + m0) = o;
    }
}

// out[z] = P[z] @ V[z] -> g_y[b, n, h*HD + d] (tf32-rounded for proj)
__global__ void __launch_bounds__(128, 2) k_pv() {
    const int z = blockIdx.z;
    const int row0 = blockIdx.y * 128;  // n
    float c[4][8][4] = {};
    const float* A = g_s + (size_t)z * Nq * Nq + (size_t)row0 * Nq;
    const float* B = g_v + (size_t)z * Nq * HDq;
    mma_pv64(A, B, c);

    const int b = z >> 2, h = z & 3;
    const int tid = threadIdx.x, lane = tid & 31, wid = tid >> 5;
    const int wm = (wid & 1) * 64, wn = (wid >> 1) * 64;
    const int lr = lane >> 2, lc = lane & 3;
#pragma unroll
    for (int t = 0; t < 4; t++)
#pragma unroll
        for (int u = 0; u < 8; u++) {
            const int d = wn + u * 8 + 2 * lc;
#pragma unroll
            for (int half = 0; half < 2; half++) {
                const int n = row0 + wm + t * 16 + lr + half * 8;
                const size_t base = ((size_t)b * Nq + n) * Cq + h * HDq + d;
                g_y[base]     = tfr(c[t][u][half * 2 + 0]);
                g_y[base + 1] = tfr(c[t][u][half * 2 + 1]);
            }
        }
}

// out = y @ w_proj^T + b_proj
__global__ void __launch_bounds__(128, 2)
k_proj(const float* __restrict__ bias, float* __restrict__ out) {
    const int row0 = blockIdx.y * 128;
    const int col0 = blockIdx.x * 128;
    float c[4][8][4] = {};
    mma_abt64<Cq>(g_y + (size_t)row0 * Cq, Cq, g_wp + (size_t)col0 * Cq, Cq, c);

    const int tid = threadIdx.x, lane = tid & 31, wid = tid >> 5;
    const int wm = (wid & 1) * 64, wn = (wid >> 1) * 64;
    const int lr = lane >> 2, lc = lane & 3;
#pragma unroll
    for (int t = 0; t < 4; t++)
#pragma unroll
        for (int u = 0; u < 8; u++) {
            const int col = col0 + wn + u * 8 + 2 * lc;
            const float b0 = bias[col], b1 = bias[col + 1];
#pragma unroll
            for (int half = 0; half < 2; half++) {
                const int r = row0 + wm + t * 16 + lr + half * 8;
                *(float2*)(out + (size_t)r * Cq + col) =
                    make_float2(c[t][u][half * 2 + 0] + b0, c[t][u][half * 2 + 1] + b1);
            }
        }
}

// ---------------- launch ----------------
extern "C" void kernel_launch(void* const* d_in, const int* in_sizes, int n_in,
                              void* d_out, int out_size) {
    const float* x      = (const float*)d_in[0];
    const float* w_qkv  = (const float*)d_in[1];
    const float* w_proj = (const float*)d_in[2];
    const float* b_proj = (const float*)d_in[3];
    const float* w_main = (const float*)d_in[4];
    const float* w_rest = (const float*)d_in[5];
    float* out = (float*)d_out;

    float* p_x;  cudaGetSymbolAddress((void**)&p_x,  g_x);
    float* p_wq; cudaGetSymbolAddress((void**)&p_wq, g_wq);
    float* p_wp; cudaGetSymbolAddress((void**)&p_wp, g_wp);

    dim3 blk(128);
    {
        int n4 = Bq * Nq * Cq / 4;
        k_round<<<(n4 + 255) / 256, 256>>>(x, p_x, n4);
        n4 = 3 * Cq * Cq / 4;
        k_round<<<(n4 + 255) / 256, 256>>>(w_qkv, p_wq, n4);
        n4 = Cq * Cq / 4;
        k_round<<<(n4 + 255) / 256, 256>>>(w_proj, p_wp, n4);
    }
    k_qkv<<<dim3(1536 / 128, (Bq * Nq) / 128), blk>>>();
    k_scores<<<dim3(Nq / 128, Nq / 128, Bq * Hq), blk>>>();
    k_mix_softmax<<<Bq * Nq, dim3(256)>>>(w_main, w_rest);
    k_pv<<<dim3(1, Nq / 128, Bq * Hq), blk>>>();
    k_proj<<<dim3(Cq / 128, (Bq * Nq) / 128), blk>>>(b_proj, out);
}